// round 17
// baseline (speedup 1.0000x reference)
#include <cuda_runtime.h>
#include <cuda_fp16.h>
#include <cstdint>

#define B_    2
#define T_    2048
#define D_    4096
#define H_    32
#define KVH_  8
#define DH_   128
#define QS_   (H_*DH_)
#define KS_   (KVH_*DH_)
#define QKVN_ (QS_ + 2*KS_)
#define M_    (B_*T_)

// Scratch
__device__ __half g_xh[(size_t)M_ * D_];
__device__ __half g_wh[(size_t)QKVN_ * D_];
__device__ __half g_oh[(size_t)D_ * QS_];
__device__ __half g_yh[(size_t)M_ * QS_];
__device__ __half g_Qh[(size_t)M_ * QS_];
__device__ __half g_Kh[(size_t)M_ * KS_];
__device__ __half g_Vh[(size_t)M_ * KS_];

// ---------------------------------------------------------------------------
__device__ __forceinline__ uint32_t smem_u32(const void* p) {
    uint32_t a;
    asm("{ .reg .u64 t; cvta.to.shared.u64 t, %1; cvt.u32.u64 %0, t; }"
        : "=r"(a) : "l"(p));
    return a;
}
__device__ __forceinline__ void cpasync16(uint32_t s, const void* g) {
    asm volatile("cp.async.cg.shared.global [%0], [%1], 16;" :: "r"(s), "l"(g));
}
#define CP_COMMIT() asm volatile("cp.async.commit_group;" ::: "memory")
#define CP_WAIT(N)  asm volatile("cp.async.wait_group %0;" :: "n"(N) : "memory")

#define LDSM_X4(r, addr)                                                      \
    asm volatile("ldmatrix.sync.aligned.m8n8.x4.shared.b16 {%0,%1,%2,%3}, [%4];" \
        : "=r"((r)[0]), "=r"((r)[1]), "=r"((r)[2]), "=r"((r)[3]) : "r"(addr))
#define LDSM_X4_T(r, addr)                                                    \
    asm volatile("ldmatrix.sync.aligned.m8n8.x4.trans.shared.b16 {%0,%1,%2,%3}, [%4];" \
        : "=r"((r)[0]), "=r"((r)[1]), "=r"((r)[2]), "=r"((r)[3]) : "r"(addr))

#define MMAH(d, a, b0, b1)                                                    \
    asm volatile("mma.sync.aligned.m16n8k16.row.col.f32.f16.f16.f32 "         \
        "{%0,%1,%2,%3}, {%4,%5,%6,%7}, {%8,%9}, {%0,%1,%2,%3};"               \
        : "+f"((d)[0]), "+f"((d)[1]), "+f"((d)[2]), "+f"((d)[3])              \
        : "r"((a)[0]), "r"((a)[1]), "r"((a)[2]), "r"((a)[3]), "r"(b0), "r"(b1))

__device__ __forceinline__ uint32_t packh2(float a, float b) {
    __half2 h = __floats2half2_rn(a, b);
    return *reinterpret_cast<uint32_t*>(&h);
}

// ---------------------------------------------------------------------------
// FP16 mma.sync GEMM (unchanged R15/R16 winner): CTA 128x128, BK=64, 256 thr,
// 2 CTA/SM, 3-stage ring, SW128 swizzle.
// mode 0: fp32 C. mode 1 (QKV): fused RoPE + fp16 store to head-major planes.
// ---------------------------------------------------------------------------
#define PLN_   (128 * 128)
#define STGN   (2 * PLN_)
#define GSMEM_ (3 * STGN)

__global__ __launch_bounds__(256, 2) void gemm1h_kernel(
    const __half* __restrict__ Ah, const __half* __restrict__ Bh,
    float* __restrict__ C, int M, int N, int K, int mode,
    const float* __restrict__ pcos, const float* __restrict__ psin)
{
    extern __shared__ char smem[];
    const uint32_t sbase = smem_u32(smem);
    const int tid  = threadIdx.x;
    const int lane = tid & 31;
    const int wid  = tid >> 5;
    const int wm   = wid >> 1;
    const int wn   = wid & 1;

    const int bm = blockIdx.y * 128;
    const int bn = blockIdx.x * 128;
    const int nk = K >> 6;

    const __half* gp[2] = { Ah + (size_t)bm * K, Bh + (size_t)bn * K };

    const int lrow[4] = { tid >> 3, (tid + 256) >> 3, (tid + 512) >> 3, (tid + 768) >> 3 };
    const int lseg = tid & 7;

    float acc[2][8][4];
#pragma unroll
    for (int mt = 0; mt < 2; mt++)
#pragma unroll
        for (int nt = 0; nt < 8; nt++)
#pragma unroll
            for (int q = 0; q < 4; q++) acc[mt][nt][q] = 0.0f;

    const int rowA = lane & 15;
    const int hiA  = lane >> 4;
    const int rowB = (lane & 7) + ((lane & 16) ? 8 : 0);
    const int hiB  = (lane >> 3) & 1;
    uint32_t baseA[2]; int swzA[2];
#pragma unroll
    for (int mt = 0; mt < 2; mt++) {
        int r = wm * 32 + mt * 16 + rowA;
        baseA[mt] = (uint32_t)(r * 128);
        swzA[mt]  = r & 7;
    }
    uint32_t baseB[4]; int swzB[4];
#pragma unroll
    for (int np = 0; np < 4; np++) {
        int r = wn * 64 + np * 16 + rowB;
        baseB[np] = (uint32_t)(r * 128);
        swzB[np]  = r & 7;
    }

#pragma unroll
    for (int pc = 0; pc < 2; pc++) {
        const uint32_t st = sbase + pc * STGN;
        const int k0 = pc << 6;
#pragma unroll
        for (int p = 0; p < 2; p++) {
            uint32_t sb = st + p * PLN_;
#pragma unroll
            for (int j = 0; j < 4; j++) {
                int row = lrow[j];
                uint32_t so = (uint32_t)(row * 128 + ((lseg ^ (row & 7)) << 4));
                cpasync16(sb + so, gp[p] + (size_t)row * K + k0 + lseg * 8);
            }
        }
        CP_COMMIT();
    }

    int s_cur = 0;
    for (int c = 0; c < nk; c++) {
        if (c + 1 < nk) { CP_WAIT(1); } else { CP_WAIT(0); }
        __syncthreads();

        if (c + 2 < nk) {
            int s_pre = s_cur + 2; if (s_pre >= 3) s_pre -= 3;
            const uint32_t st = sbase + s_pre * STGN;
            const int k0 = (c + 2) << 6;
#pragma unroll
            for (int p = 0; p < 2; p++) {
                uint32_t sb = st + p * PLN_;
#pragma unroll
                for (int j = 0; j < 4; j++) {
                    int row = lrow[j];
                    uint32_t so = (uint32_t)(row * 128 + ((lseg ^ (row & 7)) << 4));
                    cpasync16(sb + so, gp[p] + (size_t)row * K + k0 + lseg * 8);
                }
            }
            CP_COMMIT();
        }

        const uint32_t st   = sbase + s_cur * STGN;
        const uint32_t sA_h = st;
        const uint32_t sB_h = st + PLN_;

#pragma unroll
        for (int ks = 0; ks < 4; ks++) {
            uint32_t ah[2][4];
#pragma unroll
            for (int mt = 0; mt < 2; mt++) {
                uint32_t off = baseA[mt] +
                    (uint32_t)((((ks * 2 + hiA) ^ swzA[mt]) & 7) << 4);
                LDSM_X4(ah[mt], sA_h + off);
            }
#pragma unroll
            for (int np = 0; np < 4; np++) {
                uint32_t bh[4];
                uint32_t off = baseB[np] +
                    (uint32_t)((((ks * 2 + hiB) ^ swzB[np]) & 7) << 4);
                LDSM_X4(bh, sB_h + off);
#pragma unroll
                for (int mt = 0; mt < 2; mt++)
#pragma unroll
                    for (int hf = 0; hf < 2; hf++)
                        MMAH(acc[mt][2 * np + hf], ah[mt], bh[2 * hf], bh[2 * hf + 1]);
            }
        }
        if (++s_cur == 3) s_cur = 0;
    }

    if (mode == 0) {
#pragma unroll
        for (int mt = 0; mt < 2; mt++) {
            const int r0 = bm + wm * 32 + mt * 16 + (lane >> 2);
#pragma unroll
            for (int nt = 0; nt < 8; nt++) {
                const int col = bn + wn * 64 + nt * 8 + (lane & 3) * 2;
                *(float2*)&C[(size_t)r0 * N + col] =
                    make_float2(acc[mt][nt][0], acc[mt][nt][1]);
                *(float2*)&C[(size_t)(r0 + 8) * N + col] =
                    make_float2(acc[mt][nt][2], acc[mt][nt][3]);
            }
        }
    } else {
        const int h = bn >> 7;
#pragma unroll
        for (int mt = 0; mt < 2; mt++) {
            const int r0 = bm + wm * 32 + mt * 16 + (lane >> 2);
#pragma unroll
            for (int nt = 0; nt < 8; nt++) {
                const int cc = wn * 64 + nt * 8 + 2 * (lane & 3);
                const int i  = cc >> 1;
#pragma unroll
                for (int rr = 0; rr < 2; rr++) {
                    const int r = r0 + rr * 8;
                    const int t = r & (T_ - 1);
                    const int b = r >> 11;
                    float v0 = acc[mt][nt][rr * 2];
                    float v1 = acc[mt][nt][rr * 2 + 1];
                    if (h < 40) {
                        float cv = pcos[t * 64 + i];
                        float sv = psin[t * 64 + i];
                        float o0 = v0 * cv - v1 * sv;
                        float o1 = v0 * sv + v1 * cv;
                        v0 = o0; v1 = o1;
                    }
                    __half2 hv = __floats2half2_rn(v0, v1);
                    if (h < 32) {
                        size_t off = (((size_t)b * H_ + h) * T_ + t) * DH_ + cc;
                        *(__half2*)(g_Qh + off) = hv;
                    } else if (h < 40) {
                        size_t off = (((size_t)b * KVH_ + (h - 32)) * T_ + t) * DH_ + cc;
                        *(__half2*)(g_Kh + off) = hv;
                    } else {
                        size_t off = (((size_t)b * KVH_ + (h - 40)) * T_ + t) * DH_ + cc;
                        *(__half2*)(g_Vh + off) = hv;
                    }
                }
            }
        }
    }
}

// fp32 -> fp16, 4 float4 per thread
__global__ void tohalf_kernel(const float* __restrict__ in,
                              __half* __restrict__ hi, int n4)
{
    int base = (blockIdx.x * blockDim.x + threadIdx.x) * 4;
#pragma unroll
    for (int j = 0; j < 4; j++) {
        int idx = base + j;
        if (idx >= n4) return;
        float4 v = ((const float4*)in)[idx];
        __half2* hp = (__half2*)(hi + (size_t)idx * 4);
        hp[0] = __floats2half2_rn(v.x, v.y);
        hp[1] = __floats2half2_rn(v.z, v.w);
    }
}

// ---------------------------------------------------------------------------
// fp16 mma.sync flash attention, BM=128 (256 thr, 8 warps x 16 q-rows).
// S = Qh*Kh; PV = P*Vh. K/V tiles 64 rows, 2-stage ring, one sync/tile.
// Per-warp early-skip of fully-masked tiles.
// ---------------------------------------------------------------------------
#define AST_B 272
#define APL_  (64 * AST_B)      // 17408
#define ASTG  (2 * APL_)        // 34816 (Kh, Vh)
#define ASMEM (2 * ASTG)        // 69632

__global__ __launch_bounds__(256, 2) void attn_mma_kernel()
{
    extern __shared__ char sm[];
    const uint32_t sbase = smem_u32(sm);

    const int tid = threadIdx.x, lane = tid & 31, w = tid >> 5;
    const int qb = (int)(gridDim.x - 1 - blockIdx.x) * 128;   // largest-first
    const int h  = blockIdx.y;
    const int b  = blockIdx.z;
    const int kh = h >> 2;

    const __half* gQh = g_Qh + ((size_t)b * H_ + h) * T_ * DH_;
    const __half* gKh = g_Kh + ((size_t)b * KVH_ + kh) * T_ * DH_;
    const __half* gVh = g_Vh + ((size_t)b * KVH_ + kh) * T_ * DH_;

    // stage 128 Q rows (fills stage 0 exactly: rows contiguous at AST_B)
#pragma unroll
    for (int k = 0; k < 8; k++) {
        int id = tid + 256 * k, r = id >> 4, sg = id & 15;
        cpasync16(sbase + r * AST_B + sg * 16,
                  (const char*)(gQh + (size_t)(qb + r) * DH_) + sg * 16);
    }
    CP_COMMIT(); CP_WAIT(0);
    __syncthreads();

    uint32_t qh_[8][4];
    {
        uint32_t base = (uint32_t)((w * 16 + (lane & 15)) * AST_B + (lane >> 4) * 16);
#pragma unroll
        for (int ks = 0; ks < 8; ks++)
            LDSM_X4(qh_[ks], sbase + base + ks * 32);
    }
    __syncthreads();

    const int last  = (qb >> 6) + 1;                 // tiles 0..last
    const int lastw = (qb + w * 16) >> 6;            // this warp's diagonal tile

    // prologue: prefetch tile 0 into stage 0
#pragma unroll
    for (int k = 0; k < 4; k++) {
        int id = tid + 256 * k, r = id >> 4, sg = id & 15;
        size_t grow = (size_t)r * DH_;
        uint32_t soff = (uint32_t)(r * AST_B + sg * 16);
        cpasync16(sbase + soff,        (const char*)(gKh + grow) + sg * 16);
        cpasync16(sbase + APL_ + soff, (const char*)(gVh + grow) + sg * 16);
    }
    CP_COMMIT();

    float o[16][4];
#pragma unroll
    for (int nt = 0; nt < 16; nt++)
#pragma unroll
        for (int q = 0; q < 4; q++) o[nt][q] = 0.0f;
    float m0 = -1e30f, m1 = -1e30f, l0 = 0.0f, l1 = 0.0f;

    const int rowB = (lane & 7) + ((lane & 16) ? 8 : 0);
    const int colB = ((lane >> 3) & 1) * 16;
    const int qrow0 = qb + w * 16 + (lane >> 2);
    const int qrow1 = qrow0 + 8;
    const float sc = 0.08838834764831845f;

    for (int kb = 0; kb <= last; kb++) {
        CP_WAIT(0);
        __syncthreads();

        const uint32_t stc = sbase + (uint32_t)(kb & 1) * ASTG;
        if (kb < last) {
            const uint32_t stn = sbase + (uint32_t)((kb + 1) & 1) * ASTG;
#pragma unroll
            for (int k = 0; k < 4; k++) {
                int id = tid + 256 * k, r = id >> 4, sg = id & 15;
                size_t grow = (size_t)((kb + 1) * 64 + r) * DH_;
                uint32_t soff = (uint32_t)(r * AST_B + sg * 16);
                cpasync16(stn + soff,        (const char*)(gKh + grow) + sg * 16);
                cpasync16(stn + APL_ + soff, (const char*)(gVh + grow) + sg * 16);
            }
            CP_COMMIT();
        }

        if (kb > lastw) continue;   // fully masked for this warp

        const uint32_t sKh = stc;
        const uint32_t sVh = stc + APL_;

        float s[8][4];
#pragma unroll
        for (int nt = 0; nt < 8; nt++)
#pragma unroll
            for (int q = 0; q < 4; q++) s[nt][q] = 0.0f;

#pragma unroll
        for (int ks = 0; ks < 8; ks++) {
            uint32_t kfh[4][4];
#pragma unroll
            for (int pr = 0; pr < 4; pr++) {
                uint32_t off = (uint32_t)((pr * 16 + rowB) * AST_B + colB + ks * 32);
                LDSM_X4(kfh[pr], sKh + off);
            }
#pragma unroll
            for (int pr = 0; pr < 4; pr++)
#pragma unroll
                for (int hf = 0; hf < 2; hf++)
                    MMAH(s[2 * pr + hf], qh_[ks], kfh[pr][2 * hf], kfh[pr][2 * hf + 1]);
        }

        float mx0 = -1e30f, mx1 = -1e30f;
        const bool dg = (kb == lastw);
#pragma unroll
        for (int nt = 0; nt < 8; nt++) {
            int c0 = kb * 64 + nt * 8 + 2 * (lane & 3);
#pragma unroll
            for (int q = 0; q < 4; q++) s[nt][q] *= sc;
            if (dg) {
                if (c0     > qrow0) s[nt][0] = -1e30f;
                if (c0 + 1 > qrow0) s[nt][1] = -1e30f;
                if (c0     > qrow1) s[nt][2] = -1e30f;
                if (c0 + 1 > qrow1) s[nt][3] = -1e30f;
            }
            mx0 = fmaxf(mx0, fmaxf(s[nt][0], s[nt][1]));
            mx1 = fmaxf(mx1, fmaxf(s[nt][2], s[nt][3]));
        }
        mx0 = fmaxf(mx0, __shfl_xor_sync(0xffffffffu, mx0, 1));
        mx0 = fmaxf(mx0, __shfl_xor_sync(0xffffffffu, mx0, 2));
        mx1 = fmaxf(mx1, __shfl_xor_sync(0xffffffffu, mx1, 1));
        mx1 = fmaxf(mx1, __shfl_xor_sync(0xffffffffu, mx1, 2));

        float mn0 = fmaxf(m0, mx0), mn1 = fmaxf(m1, mx1);
        float cr0 = __expf(m0 - mn0), cr1 = __expf(m1 - mn1);
        float sum0 = 0.0f, sum1 = 0.0f;
#pragma unroll
        for (int nt = 0; nt < 8; nt++) {
            s[nt][0] = __expf(s[nt][0] - mn0);
            s[nt][1] = __expf(s[nt][1] - mn0);
            s[nt][2] = __expf(s[nt][2] - mn1);
            s[nt][3] = __expf(s[nt][3] - mn1);
            sum0 += s[nt][0] + s[nt][1];
            sum1 += s[nt][2] + s[nt][3];
        }
        sum0 += __shfl_xor_sync(0xffffffffu, sum0, 1);
        sum0 += __shfl_xor_sync(0xffffffffu, sum0, 2);
        sum1 += __shfl_xor_sync(0xffffffffu, sum1, 1);
        sum1 += __shfl_xor_sync(0xffffffffu, sum1, 2);
        l0 = l0 * cr0 + sum0;  m0 = mn0;
        l1 = l1 * cr1 + sum1;  m1 = mn1;
#pragma unroll
        for (int nt = 0; nt < 16; nt++) {
            o[nt][0] *= cr0; o[nt][1] *= cr0;
            o[nt][2] *= cr1; o[nt][3] *= cr1;
        }

#pragma unroll
        for (int ks = 0; ks < 4; ks++) {
            uint32_t p[4];
            p[0] = packh2(s[2 * ks][0],     s[2 * ks][1]);
            p[1] = packh2(s[2 * ks][2],     s[2 * ks][3]);
            p[2] = packh2(s[2 * ks + 1][0], s[2 * ks + 1][1]);
            p[3] = packh2(s[2 * ks + 1][2], s[2 * ks + 1][3]);
            uint32_t vb = (uint32_t)((ks * 16 + (lane & 15)) * AST_B + (lane >> 4) * 16);
#pragma unroll
            for (int np = 0; np < 8; np++) {
                uint32_t vfh[4];
                LDSM_X4_T(vfh, sVh + vb + np * 32);
                MMAH(o[2 * np],     p, vfh[0], vfh[1]);
                MMAH(o[2 * np + 1], p, vfh[2], vfh[3]);
            }
        }
    }

    float i0 = 1.0f / l0, i1 = 1.0f / l1;
    size_t r0 = (size_t)(b * T_ + qb + w * 16 + (lane >> 2)) * QS_ + h * DH_ + 2 * (lane & 3);
    size_t r1 = r0 + (size_t)8 * QS_;
#pragma unroll
    for (int nt = 0; nt < 16; nt++) {
        int cc = nt * 8;
        *(__half2*)(g_yh + r0 + cc) = __floats2half2_rn(o[nt][0] * i0, o[nt][1] * i0);
        *(__half2*)(g_yh + r1 + cc) = __floats2half2_rn(o[nt][2] * i1, o[nt][3] * i1);
    }
}

// ----------------------------------------------------------------------------
extern "C" void kernel_launch(void* const* d_in, const int* in_sizes, int n_in,
                              void* d_out, int out_size)
{
    const float* x    = (const float*)d_in[0];
    const float* fcos = (const float*)d_in[1];
    const float* fsin = (const float*)d_in[2];
    const float* wqkv = (const float*)d_in[3];
    const float* wo   = (const float*)d_in[4];
    float* out = (float*)d_out;

    __half *xh, *wh, *oh, *yh;
    cudaGetSymbolAddress((void**)&xh,  g_xh);
    cudaGetSymbolAddress((void**)&wh,  g_wh);
    cudaGetSymbolAddress((void**)&oh,  g_oh);
    cudaGetSymbolAddress((void**)&yh,  g_yh);

    cudaFuncSetAttribute(gemm1h_kernel,
                         cudaFuncAttributeMaxDynamicSharedMemorySize, GSMEM_);
    cudaFuncSetAttribute(attn_mma_kernel,
                         cudaFuncAttributeMaxDynamicSharedMemorySize, ASMEM);

    {
        int n4 = (M_ * D_) / 4;
        tohalf_kernel<<<(n4 / 4 + 255) / 256, 256>>>(x, xh, n4);
        n4 = (QKVN_ * D_) / 4;
        tohalf_kernel<<<(n4 / 4 + 255) / 256, 256>>>(wqkv, wh, n4);
        n4 = (D_ * QS_) / 4;
        tohalf_kernel<<<(n4 / 4 + 255) / 256, 256>>>(wo, oh, n4);
    }

    // QKV GEMM with fused RoPE epilogue (mode 1)
    gemm1h_kernel<<<dim3(QKVN_ / 128, M_ / 128), 256, GSMEM_>>>(
        xh, wh, nullptr, M_, QKVN_, D_, 1, fcos, fsin);

    attn_mma_kernel<<<dim3(T_ / 128, H_, B_), 256, ASMEM>>>();

    // output GEMM (mode 0)
    gemm1h_kernel<<<dim3(D_ / 128, M_ / 128), 256, GSMEM_>>>(
        yh, oh, out, M_, D_, QS_, 0, nullptr, nullptr);
}